// round 3
// baseline (speedup 1.0000x reference)
#include <cuda_runtime.h>

// Problem dims (fixed by the dataset)
#define TT 512
#define NN 64
#define DD 1024
#define HH 1024
#define GG 4096        // 4*H

#define NBLK 128       // persistent blocks (<= 148 SMs -> all co-resident)
#define KS 8           // K splits for recurrent GEMM
#define KC (HH / KS)   // 128
#define CGRP 16        // column groups
#define CW (GG / CGRP) // 256 cols per group

// Scratch (device globals: allocation-free per harness rules)
__device__ float g_xw[(size_t)TT * NN * GG];   // (T*N, 4H) precomputed x@Wx + b
__device__ float g_part[KS][NN * GG];          // split-K partials of h@Wh
__device__ float g_h[NN * HH];                 // current hidden state
__device__ unsigned g_count;                   // grid barrier counter
__device__ volatile unsigned g_gen;            // grid barrier generation

// ---------------------------------------------------------------------------
// packed f32x2 helpers (FFMA2 path — 2x fp32 FMA throughput vs FFMA-3reg)
// ---------------------------------------------------------------------------
__device__ __forceinline__ void fma2(float2& acc, unsigned long long a, const float2& b) {
    asm("fma.rn.f32x2 %0, %1, %2, %0;"
        : "+l"(reinterpret_cast<unsigned long long&>(acc))
        : "l"(a), "l"(reinterpret_cast<const unsigned long long&>(b)));
}
__device__ __forceinline__ unsigned long long dup2(float a) {
    unsigned long long r;
    asm("mov.b64 %0, {%1, %1};" : "=l"(r) : "f"(a));
    return r;
}

__device__ __forceinline__ float sigm(float x) { return 1.f / (1.f + __expf(-x)); }
__device__ __forceinline__ float tanh_(float x) { return 2.f / (1.f + __expf(-2.f * x)) - 1.f; }

// ---------------------------------------------------------------------------
// software grid barrier (all NBLK blocks co-resident by construction)
// ---------------------------------------------------------------------------
__device__ __forceinline__ void grid_sync() {
    __syncthreads();
    if (threadIdx.x == 0) {
        __threadfence();
        unsigned my = g_gen;
        if (atomicAdd(&g_count, 1) == NBLK - 1) {
            g_count = 0;
            __threadfence();
            g_gen = my + 1;
        } else {
            while (g_gen == my) { __nanosleep(32); }
        }
        __threadfence();
    }
    __syncthreads();
}

// ---------------------------------------------------------------------------
// xW GEMM: g_xw[(t*64+n)*4096 + g] = sum_d x[n][t][d]*Wx[d][g] + b[g]
// M = 32768, N = 4096, K = 1024. 128x128 tile, 256 thr, 8x8 microtile (FFMA2).
// ---------------------------------------------------------------------------
__global__ __launch_bounds__(256) void xw_gemm(const float* __restrict__ x,
                                               const float* __restrict__ Wx,
                                               const float* __restrict__ b) {
    __shared__ float As[8][132];
    __shared__ float Bs[8][128];

    const int tid = threadIdx.x;
    const int ry = tid >> 4;   // 0..15
    const int cx = tid & 15;   // 0..15
    const int m0 = blockIdx.y * 128;
    const int nc0 = blockIdx.x * 128;

    float2 acc[8][4];
    #pragma unroll
    for (int i = 0; i < 8; i++)
        #pragma unroll
        for (int j = 0; j < 4; j++) acc[i][j] = make_float2(0.f, 0.f);

    const int r = tid >> 1;   // 0..127 row within tile
    const int m = m0 + r;     // m = t*64 + n
    const float* arow = x + ((size_t)(m & 63) * TT + (size_t)(m >> 6)) * DD;
    const int kq = (tid & 1) * 4;
    const int kr = tid >> 5;           // 0..7
    const int cb = (tid & 31) * 4;     // 0..124

    for (int k0 = 0; k0 < DD; k0 += 8) {
        float4 va = *(const float4*)(arow + k0 + kq);
        As[kq + 0][r] = va.x;
        As[kq + 1][r] = va.y;
        As[kq + 2][r] = va.z;
        As[kq + 3][r] = va.w;
        *(float4*)&Bs[kr][cb] =
            *(const float4*)(Wx + (size_t)(k0 + kr) * GG + nc0 + cb);
        __syncthreads();

        #pragma unroll
        for (int k = 0; k < 8; ++k) {
            float4 a0 = *(float4*)&As[k][ry * 4];
            float4 a1 = *(float4*)&As[k][64 + ry * 4];
            unsigned long long A[8] = {dup2(a0.x), dup2(a0.y), dup2(a0.z), dup2(a0.w),
                                       dup2(a1.x), dup2(a1.y), dup2(a1.z), dup2(a1.w)};
            float2 bb[4];
            *(float4*)&bb[0] = *(float4*)&Bs[k][cx * 4];        // cols 4cx..4cx+3
            *(float4*)&bb[2] = *(float4*)&Bs[k][64 + cx * 4];   // cols 64+4cx..
            #pragma unroll
            for (int i = 0; i < 8; i++)
                #pragma unroll
                for (int j = 0; j < 4; j++) fma2(acc[i][j], A[i], bb[j]);
        }
        __syncthreads();
    }

    // epilogue with bias. col base per fragment j:
    const int colj[4] = {cx * 4, cx * 4 + 2, 64 + cx * 4, 64 + cx * 4 + 2};
    float2 bias[4];
    #pragma unroll
    for (int j = 0; j < 4; j++) bias[j] = *(const float2*)&b[nc0 + colj[j]];

    #pragma unroll
    for (int i = 0; i < 8; i++) {
        int row = (i < 4) ? (ry * 4 + i) : (64 + ry * 4 + (i - 4));
        size_t base = (size_t)(m0 + row) * GG + nc0;
        #pragma unroll
        for (int j = 0; j < 4; j++) {
            float2 v = make_float2(acc[i][j].x + bias[j].x, acc[i][j].y + bias[j].y);
            *(float2*)&g_xw[base + colj[j]] = v;
        }
    }
}

// ---------------------------------------------------------------------------
// Persistent LSTM recurrence. 128 blocks x 256 threads.
// Per step: phase A = split-K GEMM (block -> 64x256 col tile, K chunk 128),
//           grid_sync, phase B = gates + h/c/out update, grid_sync.
// c lives in registers (static thread->element map across all steps).
// ---------------------------------------------------------------------------
__global__ __launch_bounds__(256, 1) void lstm_persistent(
    const float* __restrict__ h0,
    const float* __restrict__ Wh,
    float* __restrict__ out) {
    __shared__ float As[8][68];      // [k][row 0..63]
    __shared__ float2 Bs2[8][128];   // [k][col pair 0..127] (256 cols)

    const int tid = threadIdx.x;
    const int blk = blockIdx.x;
    const int cg = blk >> 3;           // 0..15 column group
    const int ks = blk & 7;            // 0..7  K split
    const int nc0 = cg * CW;
    const int kbase = ks * KC;

    // gate-phase assignment: 2 consecutive elems per thread
    const int ge = (blk * 256 + tid) * 2;   // 0..65534
    const int gn = ge >> 10;                // batch row
    const int gj = ge & 1023;               // hidden index (even)

    // micro-tile thread coords
    const int ry = tid >> 5;   // warp id 0..7 -> rows {4ry..4ry+3, 32+4ry..}
    const int cx = tid & 31;   // lane -> col pairs {cx, cx+32, cx+64, cx+96}

    // staging load coords
    const int a_row = tid >> 2;        // 0..63
    const int a_k = (tid & 3) * 2;     // 0,2,4,6
    const int b_kr = tid >> 5;         // 0..7
    const int b_cb = (tid & 31) * 8;   // 0..248

    // init h from h0; c = 0 in registers
    float2 c = make_float2(0.f, 0.f);
    *(float2*)&g_h[ge] = *(const float2*)&h0[ge];
    grid_sync();

    for (int t = 0; t < TT; ++t) {
        // ---------- phase A: partial GEMM ----------
        float2 acc[8][4];
        #pragma unroll
        for (int i = 0; i < 8; i++)
            #pragma unroll
            for (int j = 0; j < 4; j++) acc[i][j] = make_float2(0.f, 0.f);

        for (int k0 = 0; k0 < KC; k0 += 8) {
            float2 hv = *(const float2*)&g_h[(size_t)a_row * HH + kbase + k0 + a_k];
            As[a_k][a_row] = hv.x;
            As[a_k + 1][a_row] = hv.y;
            const float* wsrc = Wh + (size_t)(kbase + k0 + b_kr) * GG + nc0 + b_cb;
            *(float4*)&Bs2[b_kr][b_cb >> 1] = *(const float4*)wsrc;
            *(float4*)&Bs2[b_kr][(b_cb >> 1) + 2] = *(const float4*)(wsrc + 4);
            __syncthreads();

            #pragma unroll
            for (int k = 0; k < 8; ++k) {
                float4 a0 = *(float4*)&As[k][4 * ry];        // broadcast in warp
                float4 a1 = *(float4*)&As[k][32 + 4 * ry];
                unsigned long long A[8] = {dup2(a0.x), dup2(a0.y), dup2(a0.z), dup2(a0.w),
                                           dup2(a1.x), dup2(a1.y), dup2(a1.z), dup2(a1.w)};
                float2 bb[4] = {Bs2[k][cx], Bs2[k][cx + 32],
                                Bs2[k][cx + 64], Bs2[k][cx + 96]};
                #pragma unroll
                for (int i = 0; i < 8; i++)
                    #pragma unroll
                    for (int j = 0; j < 4; j++) fma2(acc[i][j], A[i], bb[j]);
            }
            __syncthreads();
        }

        // store partial tile
        {
            float* dst = g_part[ks];
            #pragma unroll
            for (int i = 0; i < 8; i++) {
                int row = (i < 4) ? (4 * ry + i) : (32 + 4 * ry + (i - 4));
                size_t base = (size_t)row * GG + nc0;
                #pragma unroll
                for (int j = 0; j < 4; j++)
                    *(float2*)&dst[base + j * 64 + 2 * cx] = acc[i][j];
            }
        }
        grid_sync();

        // ---------- phase B: gates ----------
        {
            const float* xw = g_xw + (size_t)t * NN * GG;
            size_t bi = (size_t)gn * GG + gj;
            float2 pi = *(const float2*)&xw[bi];
            float2 pf = *(const float2*)&xw[bi + HH];
            float2 po = *(const float2*)&xw[bi + 2 * HH];
            float2 pg = *(const float2*)&xw[bi + 3 * HH];
            #pragma unroll
            for (int s = 0; s < KS; ++s) {
                const float* p = g_part[s];
                float2 v;
                v = *(const float2*)&p[bi];          pi.x += v.x; pi.y += v.y;
                v = *(const float2*)&p[bi + HH];     pf.x += v.x; pf.y += v.y;
                v = *(const float2*)&p[bi + 2 * HH]; po.x += v.x; po.y += v.y;
                v = *(const float2*)&p[bi + 3 * HH]; pg.x += v.x; pg.y += v.y;
            }
            float i0 = sigm(pi.x), f0 = sigm(pf.x), o0 = sigm(po.x), q0 = tanh_(pg.x);
            float i1 = sigm(pi.y), f1 = sigm(pf.y), o1 = sigm(po.y), q1 = tanh_(pg.y);
            c.x = f0 * c.x + i0 * q0;
            c.y = f1 * c.y + i1 * q1;
            float2 hv = make_float2(o0 * tanh_(c.x), o1 * tanh_(c.y));
            *(float2*)&g_h[ge] = hv;
            *(float2*)&out[((size_t)gn * TT + t) * HH + gj] = hv;
        }
        grid_sync();
    }
}

// ---------------------------------------------------------------------------
// launch: exactly 2 kernel nodes in the graph
// ---------------------------------------------------------------------------
extern "C" void kernel_launch(void* const* d_in, const int* in_sizes, int n_in,
                              void* d_out, int out_size) {
    const float* x  = (const float*)d_in[0];   // (N,T,D)
    const float* h0 = (const float*)d_in[1];   // (N,H)
    const float* Wx = (const float*)d_in[2];   // (D,4H)
    const float* Wh = (const float*)d_in[3];   // (H,4H)
    const float* b  = (const float*)d_in[4];   // (4H,)
    float* out = (float*)d_out;                // (N,T,H)

    xw_gemm<<<dim3(GG / 128, (TT * NN) / 128), 256>>>(x, Wx, b);
    lstm_persistent<<<NBLK, 256>>>(h0, Wh, out);
}

// round 4
// speedup vs baseline: 1.1084x; 1.1084x over previous
#include <cuda_runtime.h>

// Problem dims (fixed by the dataset)
#define TT 512
#define NN 64
#define DD 1024
#define HH 1024
#define GG 4096        // 4*H

#define NBLK 128       // persistent blocks, 1/SM (smem-bound), all co-resident
#define KS 8           // K splits for recurrent GEMM
#define KC (HH / KS)   // 128
#define CGRP 16        // column groups
#define CW (GG / CGRP) // 256 cols per group

// dynamic smem: Wh slice (KC*CW floats) + duplicated A stage (KC*64 float2)
#define SMEM_BYTES (KC * CW * 4 + KC * 64 * 8)   // 131072 + 65536 = 196608

// Scratch (device globals: allocation-free per harness rules)
__device__ float g_xw[(size_t)TT * NN * GG];   // (T*N, 4H) precomputed x@Wx + b
__device__ float g_part[KS][NN * GG];          // split-K partials of h@Wh
__device__ float g_h[NN * HH];                 // current hidden state
__device__ unsigned g_count;                   // grid barrier counter
__device__ volatile unsigned g_gen;            // grid barrier generation

// ---------------------------------------------------------------------------
// packed f32x2 helpers (FFMA2 path — 2x fp32 FMA throughput vs FFMA-3reg)
// ---------------------------------------------------------------------------
__device__ __forceinline__ void fma2(float2& acc, unsigned long long a, const float2& b) {
    asm("fma.rn.f32x2 %0, %1, %2, %0;"
        : "+l"(reinterpret_cast<unsigned long long&>(acc))
        : "l"(a), "l"(reinterpret_cast<const unsigned long long&>(b)));
}
__device__ __forceinline__ unsigned long long dup2(float a) {
    unsigned long long r;
    asm("mov.b64 %0, {%1, %1};" : "=l"(r) : "f"(a));
    return r;
}

__device__ __forceinline__ float sigm(float x) { return 1.f / (1.f + __expf(-x)); }
__device__ __forceinline__ float tanh_(float x) { return 2.f / (1.f + __expf(-2.f * x)) - 1.f; }

// ---------------------------------------------------------------------------
// software grid barrier (all NBLK blocks co-resident by construction)
// ---------------------------------------------------------------------------
__device__ __forceinline__ void grid_sync() {
    __syncthreads();
    if (threadIdx.x == 0) {
        __threadfence();
        unsigned my = g_gen;
        if (atomicAdd(&g_count, 1) == NBLK - 1) {
            g_count = 0;
            __threadfence();
            g_gen = my + 1;
        } else {
            while (g_gen == my) { __nanosleep(32); }
        }
        __threadfence();
    }
    __syncthreads();
}

// ---------------------------------------------------------------------------
// xW GEMM: g_xw[(t*64+n)*4096 + g] = sum_d x[n][t][d]*Wx[d][g] + b[g]
// M = 32768, N = 4096, K = 1024. 128x128 tile, 256 thr, 8x8 microtile (FFMA2),
// double-buffered smem staging (1 barrier per 8-k chunk, LDG overlapped).
// ---------------------------------------------------------------------------
__global__ __launch_bounds__(256) void xw_gemm(const float* __restrict__ x,
                                               const float* __restrict__ Wx,
                                               const float* __restrict__ b) {
    __shared__ float As[2][8][132];
    __shared__ float Bs[2][8][128];

    const int tid = threadIdx.x;
    const int ry = tid >> 4;   // 0..15
    const int cx = tid & 15;   // 0..15
    const int m0 = blockIdx.y * 128;
    const int nc0 = blockIdx.x * 128;

    float2 acc[8][4];
    #pragma unroll
    for (int i = 0; i < 8; i++)
        #pragma unroll
        for (int j = 0; j < 4; j++) acc[i][j] = make_float2(0.f, 0.f);

    const int r = tid >> 1;   // 0..127 row within tile
    const int m = m0 + r;     // m = t*64 + n
    const float* arow = x + ((size_t)(m & 63) * TT + (size_t)(m >> 6)) * DD;
    const int kq = (tid & 1) * 4;
    const int kr = tid >> 5;           // 0..7
    const int cb = (tid & 31) * 4;     // 0..124
    const float* bsrc = Wx + (size_t)kr * GG + nc0 + cb;

    // prologue: fill buffer 0
    {
        float4 va = *(const float4*)(arow + kq);
        float4 vb = *(const float4*)bsrc;
        As[0][kq + 0][r] = va.x;
        As[0][kq + 1][r] = va.y;
        As[0][kq + 2][r] = va.z;
        As[0][kq + 3][r] = va.w;
        *(float4*)&Bs[0][kr][cb] = vb;
    }
    __syncthreads();

    for (int k0 = 0; k0 < DD; k0 += 8) {
        const int cur = (k0 >> 3) & 1;
        const bool more = (k0 + 8 < DD);
        float4 nva, nvb;
        if (more) {
            nva = *(const float4*)(arow + k0 + 8 + kq);
            nvb = *(const float4*)(bsrc + (size_t)(k0 + 8) * GG);
        }

        #pragma unroll
        for (int k = 0; k < 8; ++k) {
            float4 a0 = *(float4*)&As[cur][k][ry * 4];
            float4 a1 = *(float4*)&As[cur][k][64 + ry * 4];
            unsigned long long A[8] = {dup2(a0.x), dup2(a0.y), dup2(a0.z), dup2(a0.w),
                                       dup2(a1.x), dup2(a1.y), dup2(a1.z), dup2(a1.w)};
            float2 bb[4];
            *(float4*)&bb[0] = *(float4*)&Bs[cur][k][cx * 4];
            *(float4*)&bb[2] = *(float4*)&Bs[cur][k][64 + cx * 4];
            #pragma unroll
            for (int i = 0; i < 8; i++)
                #pragma unroll
                for (int j = 0; j < 4; j++) fma2(acc[i][j], A[i], bb[j]);
        }

        if (more) {
            const int nb = cur ^ 1;
            As[nb][kq + 0][r] = nva.x;
            As[nb][kq + 1][r] = nva.y;
            As[nb][kq + 2][r] = nva.z;
            As[nb][kq + 3][r] = nva.w;
            *(float4*)&Bs[nb][kr][cb] = nvb;
        }
        __syncthreads();
    }

    // epilogue with bias
    const int colj[4] = {cx * 4, cx * 4 + 2, 64 + cx * 4, 64 + cx * 4 + 2};
    float2 bias[4];
    #pragma unroll
    for (int j = 0; j < 4; j++) bias[j] = *(const float2*)&b[nc0 + colj[j]];

    #pragma unroll
    for (int i = 0; i < 8; i++) {
        int row = (i < 4) ? (ry * 4 + i) : (64 + ry * 4 + (i - 4));
        size_t base = (size_t)(m0 + row) * GG + nc0;
        #pragma unroll
        for (int j = 0; j < 4; j++) {
            float2 v = make_float2(acc[i][j].x + bias[j].x, acc[i][j].y + bias[j].y);
            *(float2*)&g_xw[base + colj[j]] = v;
        }
    }
}

// ---------------------------------------------------------------------------
// Persistent LSTM recurrence. 128 blocks x 256 threads.
// Wh slice (128 k x 256 cols, 131 KB) lives in SMEM for ALL 512 steps.
// h stage is pre-duplicated into packed f32x2 (no dup2 MOVs in inner loop).
// Per step: stage A (1 barrier) -> 128-deep k loop, barrier-free ->
//           store partial -> grid_sync -> gates -> grid_sync.
// c lives in registers (static thread->element map across all steps).
// ---------------------------------------------------------------------------
__global__ void __launch_bounds__(256, 1) lstm_persistent(
    const float* __restrict__ h0,
    const float* __restrict__ Wh,
    float* __restrict__ out) {
    extern __shared__ float smem[];
    float* Whs = smem;                                   // [KC][CW] floats
    float2* Ash = (float2*)(smem + KC * CW);             // [KC][64] packed {h,h}

    const int tid = threadIdx.x;
    const int blk = blockIdx.x;
    const int cg = blk >> 3;           // 0..15 column group
    const int ks = blk & 7;            // 0..7  K split
    const int nc0 = cg * CW;
    const int kbase = ks * KC;

    // gate-phase assignment: 2 consecutive elems per thread
    const int ge = (blk * 256 + tid) * 2;   // 0..65534
    const int gn = ge >> 10;                // batch row
    const int gj = ge & 1023;               // hidden index (even)

    // micro-tile thread coords
    const int ry = tid >> 5;   // warp id 0..7 -> rows {4ry..4ry+3, 32+4ry..}
    const int cx = tid & 31;   // lane -> col pairs {cx, cx+32, cx+64, cx+96}

    // ---- load Wh slice into smem ONCE ----
    {
        const int kk = tid >> 1;              // 0..127
        const int cb2 = (tid & 1) * 128;      // 0 or 128
        const float* src = Wh + (size_t)(kbase + kk) * GG + nc0 + cb2;
        float* dst = Whs + kk * CW + cb2;
        #pragma unroll
        for (int i = 0; i < 32; ++i)
            *(float4*)(dst + i * 4) = *(const float4*)(src + i * 4);
    }

    // init h from h0; c = 0 in registers
    float2 c = make_float2(0.f, 0.f);
    *(float2*)&g_h[ge] = *(const float2*)&h0[ge];
    grid_sync();

    // A staging coords: row = tid&63, k block of 32
    const int a_row = tid & 63;
    const int a_kq = (tid >> 6) * 32;   // 0,32,64,96
    const float* hsrc_base = g_h + (size_t)a_row * HH + kbase + a_kq;

    for (int t = 0; t < TT; ++t) {
        // ---------- stage A: h slice -> smem, duplicated for f32x2 ----------
        #pragma unroll
        for (int i = 0; i < 8; ++i) {
            float4 hv = *(const float4*)(hsrc_base + i * 4);
            const int k4 = a_kq + i * 4;
            Ash[(k4 + 0) * 64 + a_row] = make_float2(hv.x, hv.x);
            Ash[(k4 + 1) * 64 + a_row] = make_float2(hv.y, hv.y);
            Ash[(k4 + 2) * 64 + a_row] = make_float2(hv.z, hv.z);
            Ash[(k4 + 3) * 64 + a_row] = make_float2(hv.w, hv.w);
        }
        __syncthreads();

        // ---------- phase A: partial GEMM, barrier-free ----------
        float2 acc[8][4];
        #pragma unroll
        for (int i = 0; i < 8; i++)
            #pragma unroll
            for (int j = 0; j < 4; j++) acc[i][j] = make_float2(0.f, 0.f);

        #pragma unroll 8
        for (int kk = 0; kk < KC; ++kk) {
            const unsigned long long* ak =
                (const unsigned long long*)Ash + (size_t)kk * 64;
            unsigned long long A[8];
            *(uint4*)&A[0] = *(const uint4*)(ak + 4 * ry);          // rows 4ry..+1
            *(uint4*)&A[2] = *(const uint4*)(ak + 4 * ry + 2);      // rows +2,+3
            *(uint4*)&A[4] = *(const uint4*)(ak + 32 + 4 * ry);     // rows 32+4ry..
            *(uint4*)&A[6] = *(const uint4*)(ak + 32 + 4 * ry + 2);
            const float2* bk = (const float2*)Whs + (size_t)kk * 128;
            float2 bb[4] = {bk[cx], bk[cx + 32], bk[cx + 64], bk[cx + 96]};
            #pragma unroll
            for (int i = 0; i < 8; i++)
                #pragma unroll
                for (int j = 0; j < 4; j++) fma2(acc[i][j], A[i], bb[j]);
        }

        // store partial tile
        {
            float* dst = g_part[ks];
            #pragma unroll
            for (int i = 0; i < 8; i++) {
                int row = (i < 4) ? (4 * ry + i) : (32 + 4 * ry + (i - 4));
                size_t base = (size_t)row * GG + nc0;
                #pragma unroll
                for (int j = 0; j < 4; j++)
                    *(float2*)&dst[base + j * 64 + 2 * cx] = acc[i][j];
            }
        }
        grid_sync();

        // ---------- phase B: gates ----------
        {
            const float* xw = g_xw + (size_t)t * NN * GG;
            size_t bi = (size_t)gn * GG + gj;
            float2 pi = *(const float2*)&xw[bi];
            float2 pf = *(const float2*)&xw[bi + HH];
            float2 po = *(const float2*)&xw[bi + 2 * HH];
            float2 pg = *(const float2*)&xw[bi + 3 * HH];
            #pragma unroll
            for (int s = 0; s < KS; ++s) {
                const float* p = g_part[s];
                float2 v;
                v = *(const float2*)&p[bi];          pi.x += v.x; pi.y += v.y;
                v = *(const float2*)&p[bi + HH];     pf.x += v.x; pf.y += v.y;
                v = *(const float2*)&p[bi + 2 * HH]; po.x += v.x; po.y += v.y;
                v = *(const float2*)&p[bi + 3 * HH]; pg.x += v.x; pg.y += v.y;
            }
            float i0 = sigm(pi.x), f0 = sigm(pf.x), o0 = sigm(po.x), q0 = tanh_(pg.x);
            float i1 = sigm(pi.y), f1 = sigm(pf.y), o1 = sigm(po.y), q1 = tanh_(pg.y);
            c.x = f0 * c.x + i0 * q0;
            c.y = f1 * c.y + i1 * q1;
            float2 hv = make_float2(o0 * tanh_(c.x), o1 * tanh_(c.y));
            *(float2*)&g_h[ge] = hv;
            *(float2*)&out[((size_t)gn * TT + t) * HH + gj] = hv;
        }
        grid_sync();
    }
}

// ---------------------------------------------------------------------------
// launch: exactly 2 kernel nodes in the graph
// ---------------------------------------------------------------------------
extern "C" void kernel_launch(void* const* d_in, const int* in_sizes, int n_in,
                              void* d_out, int out_size) {
    const float* x  = (const float*)d_in[0];   // (N,T,D)
    const float* h0 = (const float*)d_in[1];   // (N,H)
    const float* Wx = (const float*)d_in[2];   // (D,4H)
    const float* Wh = (const float*)d_in[3];   // (H,4H)
    const float* b  = (const float*)d_in[4];   // (4H,)
    float* out = (float*)d_out;                // (N,T,H)

    cudaFuncSetAttribute(lstm_persistent,
                         cudaFuncAttributeMaxDynamicSharedMemorySize, SMEM_BYTES);

    xw_gemm<<<dim3(GG / 128, (TT * NN) / 128), 256>>>(x, Wx, b);
    lstm_persistent<<<NBLK, 256, SMEM_BYTES>>>(h0, Wh, out);
}